// round 9
// baseline (speedup 1.0000x reference)
#include <cuda_runtime.h>
#include <cuda_bf16.h>
#include <cstdint>

#define SCORE_THRESH 0.2f
#define NMS_THRESH   0.5f
#define MAXH 15
#define MAXO 15
#define KOUT 30
#define NCLS 81
#define G    4            // CTAs per batch
#define NJ   21           // classes per CTA = ceil(81/4)
#define CAP  64           // per-class capacity (mean ~20, 64 ≈ 9.7 sigma)
#define BMAX 64
#define NOBJ (NCLS - 1)   // 80 object classes
#define NOKEYS (NOBJ * MAXO)   // 1200
#define NTHREADS 672

typedef unsigned long long u64;

// Scratch kept-keys per (batch, class); slots zero-padded every run.
__device__ u64 g_keys[BMAX * NCLS * MAXO];
// Arrival counters; never reset — each launch adds exactly G per batch, so
// (old % G == G-1) identifies the last CTA on every launch/replay.
__device__ unsigned int g_done[BMAX];

__global__ __launch_bounds__(NTHREADS, 1)
void fused_kernel(const float* __restrict__ boxes,
                  const float* __restrict__ scores,
                  const int*   __restrict__ labels,
                  float* __restrict__ out,
                  int B, int N)
{
    __shared__ u64 bucket[NJ * CAP];
    __shared__ u64 allkeys[NOKEYS];     // merge staging (last CTA only)
    __shared__ int bcnt[NJ];
    __shared__ int isLast;

    const int g    = blockIdx.x;        // class group (c % G == g)
    const int b    = blockIdx.y;
    const int tid  = threadIdx.x;
    const int wid  = tid >> 5;
    const int lane = tid & 31;
    const unsigned FULL = 0xFFFFFFFFu;

    const float4* bx4 = (const float4*)(boxes + (size_t)b * N * 4);
    const float4* sc4 = (const float4*)(scores + (size_t)b * N);
    const int4*   lb4 = (const int4*)(labels + (size_t)b * N);

    float* outBoxes  = out;                          // [B][KOUT][4]
    float* outScores = out + (size_t)B * KOUT * 4;
    float* outLabels = out + (size_t)B * KOUT * 5;
    float* outValid  = out + (size_t)B * KOUT * 6;

    if (tid < NJ) bcnt[tid] = 0;
    __syncthreads();

    // ---- Phase A: vectorized scan + scatter keys of our class group ----
    for (int i4 = tid; i4 * 4 < N; i4 += NTHREADS) {
        float4 s = sc4[i4];
        int4   l = lb4[i4];
        int i0 = i4 * 4;
        #pragma unroll
        for (int e = 0; e < 4; e++) {
            float se = (e == 0) ? s.x : (e == 1) ? s.y : (e == 2) ? s.z : s.w;
            int   le = (e == 0) ? l.x : (e == 1) ? l.y : (e == 2) ? l.z : l.w;
            if (se >= SCORE_THRESH && (le & (G - 1)) == g) {
                int j = le >> 2;
                u64 k = ((u64)__float_as_uint(se) << 32) |
                        ((u64)(unsigned)(i0 + e) << 8) | (unsigned)le;
                int p = atomicAdd(&bcnt[j], 1);
                if (p < CAP) bucket[j * CAP + p] = k;
            }
        }
    }
    __syncthreads();

    // ---- Phase B: one class per warp ----
    const int  c  = wid * G + g;
    const bool vc = (c < NCLS);
    int cnt = vc ? min(bcnt[wid], CAP) : 0;

    float kx1 = 0, ky1 = 0, kx2 = 0, ky2 = 0;   // kept box of rank `lane`
    u64 mykey = 0;
    int kC = 0;

    if (cnt > 0) {
        // 64-element bitonic sort, 2 keys/lane, descending
        u64 k0 = (lane      < cnt) ? bucket[wid * CAP + lane]      : 0ull;
        u64 k1 = (lane + 32 < cnt) ? bucket[wid * CAP + lane + 32] : 0ull;
        #pragma unroll
        for (int kk = 2; kk <= 64; kk <<= 1) {
            if (kk == 64) { if (k0 < k1) { u64 t = k0; k0 = k1; k1 = t; } }
            #pragma unroll
            for (int jj = (kk == 64) ? 16 : (kk >> 1); jj > 0; jj >>= 1) {
                bool lower = (lane & jj) == 0;
                u64 o0 = __shfl_xor_sync(FULL, k0, jj);
                u64 o1 = __shfl_xor_sync(FULL, k1, jj);
                bool d0 = ((lane)      & kk) == 0;
                bool d1 = ((lane + 32) & kk) == 0;
                k0 = (lower == d0) ? max(k0, o0) : min(k0, o0);
                k1 = (lower == d1) ? max(k1, o1) : min(k1, o1);
            }
        }

        // prefetch candidate boxes (parallel LDG)
        float4 mb0 = make_float4(0, 0, 0, 0), mb1 = make_float4(0, 0, 0, 0);
        if (lane      < cnt) mb0 = bx4[(int)((k0 >> 8) & 0xFFFFFFull)];
        if (lane + 32 < cnt) mb1 = bx4[(int)((k1 >> 8) & 0xFFFFFFull)];

        // greedy NMS
        for (int t = 0; t < cnt && kC < MAXO; t++) {
            int sl = t & 31;
            u64   ck  = __shfl_sync(FULL, (t < 32) ? k0    : k1,    sl);
            float cx1 = __shfl_sync(FULL, (t < 32) ? mb0.x : mb1.x, sl);
            float cy1 = __shfl_sync(FULL, (t < 32) ? mb0.y : mb1.y, sl);
            float cx2 = __shfl_sync(FULL, (t < 32) ? mb0.z : mb1.z, sl);
            float cy2 = __shfl_sync(FULL, (t < 32) ? mb0.w : mb1.w, sl);
            float aC  = (cx2 - cx1) * (cy2 - cy1);

            bool sup = false;
            if (lane < kC) {
                float aK  = (kx2 - kx1) * (ky2 - ky1);
                float ltx = fmaxf(cx1, kx1), lty = fmaxf(cy1, ky1);
                float rbx = fminf(cx2, kx2), rby = fminf(cy2, ky2);
                float iw  = fmaxf(rbx - ltx, 0.0f);
                float ih  = fmaxf(rby - lty, 0.0f);
                float inter = iw * ih;
                sup = inter / (aC + aK - inter + 1e-9f) > NMS_THRESH;
            }
            if (!__any_sync(FULL, sup)) {
                if (lane == kC) { kx1 = cx1; ky1 = cy1; kx2 = cx2; ky2 = cy2; mykey = ck; }
                kC++;
            }
        }
    }

    if (vc) {
        if (c == 0) {
            // humans: slots 0..14 (incl. defaults) straight from registers
            if (lane < MAXH) {
                bool v = lane < kC;
                float* ob = outBoxes + ((size_t)b * KOUT + lane) * 4;
                *(float4*)ob = v ? make_float4(kx1, ky1, kx2, ky2)
                                 : make_float4(0, 0, 0, 0);
                outScores[b * KOUT + lane] = v ? __uint_as_float((unsigned)(mykey >> 32)) : 0.0f;
                outLabels[b * KOUT + lane] = v ? 0.0f : -1.0f;
                outValid [b * KOUT + lane] = v ? 1.0f : 0.0f;
            }
        } else {
            u64* dst = g_keys + ((size_t)b * NCLS + c) * MAXO;
            if (lane < MAXO) dst[lane] = (lane < kC) ? mykey : 0ull;
        }
    }

    // ---- last-CTA election (threadFenceReduction pattern) ----
    __syncthreads();                 // all g_keys STGs issued & CTA-visible
    if (tid == 0) {
        __threadfence();             // publish this CTA's g_keys writes
        unsigned old = atomicAdd(&g_done[b], 1u);
        isLast = ((old & (G - 1)) == (G - 1)) ? 1 : 0;
        if (isLast) __threadfence(); // acquire side: order subsequent reads
    }
    __syncthreads();
    if (!isLast) return;

    // ---- merge (last CTA only): stage 1200 object keys, tournament top-15 ----
    const size_t bb = (size_t)b * NCLS * MAXO;
    for (int i = tid; i < NOKEYS; i += NTHREADS) allkeys[i] = g_keys[bb + MAXO + i];
    __syncthreads();

    if (tid < 32) {
        const int l0 = lane, l1 = lane + 32, l2 = lane + 64;
        u64 h0 = allkeys[l0 * MAXO];
        u64 h1 = allkeys[l1 * MAXO];
        u64 h2 = (lane < 16) ? allkeys[l2 * MAXO] : 0ull;
        int p0 = 0, p1 = 0, p2 = 0;

        u64 wkey = 0;
        for (int r = 0; r < MAXO; r++) {
            u64 best = max(h0, max(h1, h2));
            u64 win = best;
            #pragma unroll
            for (int o = 16; o; o >>= 1) win = max(win, __shfl_xor_sync(FULL, win, o));
            if (win == 0ull) break;
            if (lane == r) wkey = win;
            if (best == win) {        // keys unique -> exactly one lane
                if (win == h0)      { p0++; h0 = (p0 < MAXO) ? allkeys[l0 * MAXO + p0] : 0ull; }
                else if (win == h1) { p1++; h1 = (p1 < MAXO) ? allkeys[l1 * MAXO + p1] : 0ull; }
                else                { p2++; h2 = (p2 < MAXO) ? allkeys[l2 * MAXO + p2] : 0ull; }
            }
        }

        if (lane < MAXO) {
            int slot = MAXH + lane;
            bool v = (wkey != 0ull);
            float4 wb = v ? bx4[(int)((wkey >> 8) & 0xFFFFFFull)]
                          : make_float4(0, 0, 0, 0);
            float* ob = outBoxes + ((size_t)b * KOUT + slot) * 4;
            *(float4*)ob = wb;
            outScores[b * KOUT + slot] = v ? __uint_as_float((unsigned)(wkey >> 32)) : 0.0f;
            outLabels[b * KOUT + slot] = v ? (float)(int)(wkey & 0xFFull) : -1.0f;
            outValid [b * KOUT + slot] = v ? 1.0f : 0.0f;
        }
    }
}

extern "C" void kernel_launch(void* const* d_in, const int* in_sizes, int n_in,
                              void* d_out, int out_size)
{
    const float* boxes  = (const float*)d_in[0];
    const float* scores = (const float*)d_in[1];
    const int*   labels = (const int*)d_in[2];

    int B = out_size / (KOUT * 7);        // 32
    if (B <= 0) B = 1;
    if (B > BMAX) B = BMAX;
    int N = in_sizes[1] / B;              // 2048

    dim3 grid(G, B);
    fused_kernel<<<grid, NTHREADS>>>(boxes, scores, labels, (float*)d_out, B, N);
}